// round 10
// baseline (speedup 1.0000x reference)
#include <cuda_runtime.h>
#include <cuda_bf16.h>

// Problem constants (fixed by the dataset reference).
#define N_NEURONS 100000
#define AVG_CONN  500
#define N_STEPS   10
#define DECAY     0.95f

#define THREADS   1024
#define BLOCKS    ((N_NEURONS + THREADS - 1) / THREADS)   // 98 — single wave (~50 regs -> 1 blk/SM, 98 <= 148 SMs)

// Scratch state (__device__ globals; alloc-free per harness rules).
// Zero-initialized at module load; post buffers are re-zeroed by their owning
// threads within each run, so every graph replay starts from identical state.
__device__ float    g_postA[N_NEURONS];
__device__ float    g_postB[N_NEURONS];
// Grid barrier: count self-resets each barrier; gen is MONOTONIC (never reset —
// correct across graph replays since only equality vs a captured value matters,
// unsigned wraparound included).
__device__ unsigned g_bar_count;
__device__ unsigned g_bar_gen;

// Software grid barrier (software form of grid_group::sync).
// Deadlock-free because all BLOCKS blocks are co-resident (single wave).
//
// Ordering invariants:
//  - capture(my=gen) -> fence -> arrive(count): the release (which can only
//    happen after ALL arrives) is strictly after every capture, so no spinner
//    can capture the post-release generation and miss its wakeup.
//  - releaser: reset(count) -> fence -> release(gen): paired with the
//    spinner's post-spin fence, makes the count reset visible before any
//    thread can arrive at the next barrier.
__device__ __forceinline__ void grid_sync()
{
    __syncthreads();
    if (threadIdx.x == 0) {
        __threadfence();                                   // publish this block's writes
        unsigned my = atomicOr(&g_bar_gen, 0u);            // strongly-ordered capture
        __threadfence();                                   // capture BEFORE arrive
        unsigned old = atomicAdd(&g_bar_count, 1u);
        if (old == BLOCKS - 1) {
            atomicExch(&g_bar_count, 0u);                  // reset for next barrier
            __threadfence();                               // reset visible before release
            atomicAdd(&g_bar_gen, 1u);                     // release all spinners
        } else {
            // Sleep-poll: 97 blocks hammering the gen line would contend with
            // the releaser's atomic on the same LTS slice; nanosleep backs off.
            while (*(volatile unsigned*)&g_bar_gen == my) {
                __nanosleep(64);
            }
        }
        __threadfence();                                   // acquire other blocks' writes
    }
    __syncthreads();
}

// Single persistent kernel: all 10 steps, per-neuron state in registers.
// All 10 noise values are preloaded into registers BEFORE the step loop:
// noise is a pure input with no barrier dependency, so hoisting it removes
// one L2-latency load from every step's post-barrier critical path.
// Per step:
//   1. (t>0) pot += sign * post_read[i]; post_read[i] = 0   (double-buffered)
//   2. pot = pot*DECAY + nz[t] (+ external_input at t=0)
//   3. fired = pot >= th ; th = clip(th + fired*0.5 - 0.1, 1, 100)
//   4. if any lane fired: scatter 500 weighted edges per fired lane (atomicAdd)
//   5. grid_sync()  — orders scatter(t) before fold(t+1), and zero(t) before
//                     scatter into the same buffer at t+1.
// The fired-skip is exact: non-fired rows contribute identically zero to the
// segment sum, for ANY input (R7 rel_err=0.0 confirms the scatter path is
// dormant for this dataset).
__global__ void __launch_bounds__(THREADS)
brain_persistent_kernel(const float* __restrict__ ext,
                        const float* __restrict__ weights,
                        const int*   __restrict__ conn,
                        const float* __restrict__ inhib,
                        const float* __restrict__ noise,
                        const float* __restrict__ pot0,
                        const float* __restrict__ th0,
                        float*       __restrict__ out)
{
    const int i = blockIdx.x * blockDim.x + threadIdx.x;
    const bool active = (i < N_NEURONS);

    float pot = 0.0f, th = 1e30f, sign = 0.0f;   // inactive lanes: th huge -> never "fire"
    float nz[N_STEPS];
    #pragma unroll
    for (int t = 0; t < N_STEPS; t++) nz[t] = 0.0f;

    if (active) {
        pot  = pot0[i];
        th   = th0[i];
        sign = 1.0f - 2.0f * inhib[i];
        // Preload all 10 noise values (MLP=10, one burst at kernel start).
        #pragma unroll
        for (int t = 0; t < N_STEPS; t++)
            nz[t] = noise[(size_t)t * N_NEURONS + i];
    }

    #pragma unroll 1
    for (int t = 0; t < N_STEPS; t++) {
        float* post_scatter = (t & 1) ? g_postB : g_postA;
        float* post_read    = (t & 1) ? g_postA : g_postB;

        bool fired = false;
        if (active) {
            if (t > 0) {
                pot = fmaf(sign, post_read[i], pot);
                post_read[i] = 0.0f;                  // ready for reuse at t+1
            }
            pot = pot * DECAY + nz[t];
            if (t == 0) pot += ext[i];

            fired = (pot >= th);
            th = fminf(fmaxf(th + (fired ? 0.5f : 0.0f) - 0.1f, 1.0f), 100.0f);
        }

        // Warp-uniform gate: all-zero ballot -> whole warp skips the scatter
        // via one non-divergent branch. Full mask is safe: every thread of
        // the block reaches here (no early return in this kernel).
        unsigned any_fired = __ballot_sync(0xFFFFFFFFu, fired);
        if (any_fired) {
            if (fired) {
                // Cold path. Vectorized edge fetch (500 = 125*4): 8
                // independent loads in flight per unrolled iter hide L2
                // latency; no-return atomicAdd compiles to REDG.
                const float4* w4 = (const float4*)(weights + (size_t)i * AVG_CONN);
                const int4*   c4 = (const int4*)  (conn    + (size_t)i * AVG_CONN);
                #pragma unroll 5
                for (int k = 0; k < AVG_CONN / 4; k++) {
                    float4 w = w4[k];
                    int4   c = c4[k];
                    atomicAdd(&post_scatter[c.x], w.x);
                    atomicAdd(&post_scatter[c.y], w.y);
                    atomicAdd(&post_scatter[c.z], w.z);
                    atomicAdd(&post_scatter[c.w], w.w);
                }
            }
        }
        grid_sync();   // ALL threads participate, active or not
    }

    // Final fold of step 9's scatter (went into g_postB) and output.
    // Re-zero g_postB so the next graph replay starts clean.
    if (active) {
        out[i] = fmaf(sign, g_postB[i], pot);
        g_postB[i] = 0.0f;
    }
}

extern "C" void kernel_launch(void* const* d_in, const int* in_sizes, int n_in,
                              void* d_out, int out_size)
{
    // metadata order: external_input, weights, connections, inhibitory_mask,
    //                 noise, potentials0, thresholds0, steps
    const float* ext   = (const float*)d_in[0];
    const float* wts   = (const float*)d_in[1];
    const int*   conn  = (const int*)  d_in[2];
    const float* inhib = (const float*)d_in[3];
    const float* noise = (const float*)d_in[4];
    const float* pot0  = (const float*)d_in[5];
    const float* th0   = (const float*)d_in[6];
    // d_in[7] = steps (constant 10 in this dataset; compiled in — reading a
    // device scalar back would require a sync, which breaks graph capture).

    brain_persistent_kernel<<<BLOCKS, THREADS>>>(
        ext, wts, conn, inhib, noise, pot0, th0, (float*)d_out);

    (void)in_sizes; (void)n_in; (void)out_size;
}

// round 13
// speedup vs baseline: 1.2477x; 1.2477x over previous
#include <cuda_runtime.h>
#include <cuda_bf16.h>

// Problem constants (fixed by the dataset reference).
#define N_NEURONS 100000
#define AVG_CONN  500
#define N_STEPS   10
#define DECAY     0.95f

#define THREADS   1024
#define BLOCKS    ((N_NEURONS + THREADS - 1) / THREADS)   // 98 — single wave (regs=32 measured -> >=1 blk/SM)

// Scratch state (__device__ globals; alloc-free per harness rules).
// Zero-initialized at module load; post buffers are re-zeroed by their owning
// threads within each run, so every graph replay starts from identical state.
__device__ float    g_postA[N_NEURONS];
__device__ float    g_postB[N_NEURONS];
// Grid barrier: count self-resets each barrier; gen is MONOTONIC (never reset —
// correct across graph replays since each run captures its own gen_base).
__device__ unsigned g_bar_count;
__device__ unsigned g_bar_gen;

// ---- Scoped-atomic primitives: fences folded into the atomics. The R10
// ---- profile showed the explicit-membar barrier costing ~3.3us each; this
// ---- version has ONE acq_rel atomic on the arrive path and a fence-free
// ---- release/acquire pair on the wakeup path.
__device__ __forceinline__ unsigned atom_add_acq_rel(unsigned* p, unsigned v) {
    unsigned old;
    asm volatile("atom.add.acq_rel.gpu.global.u32 %0, [%1], %2;"
                 : "=r"(old) : "l"(p), "r"(v) : "memory");
    return old;
}
__device__ __forceinline__ void st_relaxed_gpu(unsigned* p, unsigned v) {
    asm volatile("st.relaxed.gpu.global.u32 [%0], %1;" :: "l"(p), "r"(v) : "memory");
}
__device__ __forceinline__ void red_add_release(unsigned* p, unsigned v) {
    asm volatile("red.add.release.gpu.global.u32 [%0], %1;" :: "l"(p), "r"(v) : "memory");
}
__device__ __forceinline__ unsigned ld_acquire_gpu(const unsigned* p) {
    unsigned v;
    asm volatile("ld.acquire.gpu.global.u32 %0, [%1];" : "=r"(v) : "l"(p) : "memory");
    return v;
}

// Single persistent kernel: all 10 steps, per-neuron state in registers.
// Grid barrier correctness:
//  - bar.sync before the leader's arrive makes all block threads' writes
//    happen-before the release-arrive (PTX cumulativity), so one release
//    publishes the whole block's scatters/zeros.
//  - arrive is acq_rel: the last arriver (releaser) also ACQUIRES all other
//    blocks' released writes before it proceeds.
//  - releaser: relaxed count=0, then release-add gen. Spinners' acquire-load
//    of gen observes both the reset and all published data (a block can only
//    reach barrier t+1 after acquiring the t release, which carries the reset).
//  - gen_base is captured ONCE at kernel start (fence-ordered before the
//    first arrive); barrier t's spin target is gen_base + t + 1, wrap-safe.
//  - Spin is a PURE acquire-load loop — no __nanosleep. Expected wait is
//    <1us; sleep quantization was a candidate cause of the R10 3.3us/barrier
//    cost. 97 pollers on one L2 line at ~234cyc/poll is well within one LTS
//    slice's read throughput.
//  - Deadlock-free: 98 blocks, regs=32 measured -> single co-resident wave.
__global__ void __launch_bounds__(THREADS)
brain_persistent_kernel(const float* __restrict__ ext,
                        const float* __restrict__ weights,
                        const int*   __restrict__ conn,
                        const float* __restrict__ inhib,
                        const float* __restrict__ noise,
                        const float* __restrict__ pot0,
                        const float* __restrict__ th0,
                        float*       __restrict__ out)
{
    const int i = blockIdx.x * blockDim.x + threadIdx.x;
    const bool active = (i < N_NEURONS);

    unsigned gen_base = 0;
    if (threadIdx.x == 0) {
        gen_base = ld_acquire_gpu(&g_bar_gen);   // stable: no release can occur
        __threadfence();                         // before this block's first arrive
    }

    float pot = 0.0f, th = 1e30f, sign = 0.0f;   // inactive lanes never "fire"
    float nz[N_STEPS];
    #pragma unroll
    for (int t = 0; t < N_STEPS; t++) nz[t] = 0.0f;

    if (active) {
        pot  = pot0[i];
        th   = th0[i];
        sign = 1.0f - 2.0f * inhib[i];
        // Preload all 10 noise values (no barrier dependency; MLP=10 burst,
        // takes the noise load off every step's post-barrier critical path).
        #pragma unroll
        for (int t = 0; t < N_STEPS; t++)
            nz[t] = noise[(size_t)t * N_NEURONS + i];
    }

    #pragma unroll 1
    for (int t = 0; t < N_STEPS; t++) {
        float* post_scatter = (t & 1) ? g_postB : g_postA;
        float* post_read    = (t & 1) ? g_postA : g_postB;

        bool fired = false;
        if (active) {
            if (t > 0) {
                pot = fmaf(sign, post_read[i], pot);
                post_read[i] = 0.0f;                  // ready for reuse at t+1
            }
            pot = pot * DECAY + nz[t];
            if (t == 0) pot += ext[i];

            fired = (pot >= th);
            th = fminf(fmaxf(th + (fired ? 0.5f : 0.0f) - 0.1f, 1.0f), 100.0f);
        }

        // Warp-uniform gate: all-zero ballot -> whole warp skips the scatter
        // via one non-divergent branch (R7/R10 rel_err=0.0: path is dormant
        // for this dataset; remains exact for any input).
        unsigned any_fired = __ballot_sync(0xFFFFFFFFu, fired);
        if (any_fired) {
            if (fired) {
                const float4* w4 = (const float4*)(weights + (size_t)i * AVG_CONN);
                const int4*   c4 = (const int4*)  (conn    + (size_t)i * AVG_CONN);
                #pragma unroll 5
                for (int k = 0; k < AVG_CONN / 4; k++) {
                    float4 w = w4[k];
                    int4   c = c4[k];
                    atomicAdd(&post_scatter[c.x], w.x);
                    atomicAdd(&post_scatter[c.y], w.y);
                    atomicAdd(&post_scatter[c.z], w.z);
                    atomicAdd(&post_scatter[c.w], w.w);
                }
            }
        }

        // ---- slim grid barrier ----
        __syncthreads();
        if (threadIdx.x == 0) {
            unsigned old = atom_add_acq_rel(&g_bar_count, 1u);
            if (old == BLOCKS - 1) {
                st_relaxed_gpu(&g_bar_count, 0u);     // ordered by release below
                red_add_release(&g_bar_gen, 1u);      // release all spinners
            } else {
                const unsigned target = gen_base + (unsigned)t + 1u;
                while ((int)(ld_acquire_gpu(&g_bar_gen) - target) < 0) {
                    // pure spin — no nanosleep (quantization suspect from R10)
                }
            }
        }
        __syncthreads();
        // ---------------------------
    }

    // Final fold of step 9's scatter (went into g_postB) and output.
    // Re-zero g_postB so the next graph replay starts clean.
    if (active) {
        out[i] = fmaf(sign, g_postB[i], pot);
        g_postB[i] = 0.0f;
    }
}

extern "C" void kernel_launch(void* const* d_in, const int* in_sizes, int n_in,
                              void* d_out, int out_size)
{
    // metadata order: external_input, weights, connections, inhibitory_mask,
    //                 noise, potentials0, thresholds0, steps
    const float* ext   = (const float*)d_in[0];
    const float* wts   = (const float*)d_in[1];
    const int*   conn  = (const int*)  d_in[2];
    const float* inhib = (const float*)d_in[3];
    const float* noise = (const float*)d_in[4];
    const float* pot0  = (const float*)d_in[5];
    const float* th0   = (const float*)d_in[6];
    // d_in[7] = steps (constant 10 in this dataset; compiled in — reading a
    // device scalar back would require a sync, which breaks graph capture).

    brain_persistent_kernel<<<BLOCKS, THREADS>>>(
        ext, wts, conn, inhib, noise, pot0, th0, (float*)d_out);

    (void)in_sizes; (void)n_in; (void)out_size;
}